// round 1
// baseline (speedup 1.0000x reference)
#include <cuda_runtime.h>
#include <math.h>

#define BATCH 128
#define TTOK  64
#define ITOK  196
#define DIM   512
#define TEMP  0.07f

// Scratch: maxsim matrix S[b1(text)][b2(image)]
__device__ float g_S[BATCH * BATCH];

// One block per (b1, b2). 256 threads = 16(tx over i) x 16(ty over t).
// Each thread accumulates a 4(t) x 13(i) register tile; i = tx + 16*c, t = ty*4 + r.
__global__ __launch_bounds__(256, 2)
void maxsim_kernel(const float* __restrict__ image, const float* __restrict__ text) {
    const int b2 = blockIdx.x;   // image batch
    const int b1 = blockIdx.y;   // text batch
    const int tid = threadIdx.x;
    const int tx = tid & 15;
    const int ty = tid >> 4;

    __shared__ float sT[16][68];    // [k][t], pad 68 keeps float4 alignment
    __shared__ float sI[16][208];   // [k][i], i padded 196 -> 208
    __shared__ float tmax[TTOK];

    // Zero the padded image columns once (i in [196,208))
    for (int idx = tid; idx < 16 * 12; idx += 256) {
        int k = idx / 12;
        int i = 196 + (idx % 12);
        sI[k][i] = 0.0f;
    }

    float acc[4][13];
#pragma unroll
    for (int r = 0; r < 4; ++r)
#pragma unroll
        for (int c = 0; c < 13; ++c) acc[r][c] = 0.0f;

    const float* tbase = text  + (size_t)b1 * TTOK * DIM;
    const float* ibase = image + (size_t)b2 * ITOK * DIM;

    const int trow = tid >> 2;   // 0..63  (text token this thread loads)
    const int tq   = tid & 3;    // quad of 4 k-values

    for (int kc = 0; kc < DIM; kc += 16) {
        __syncthreads();   // protect smem reads of previous chunk

        // Load text chunk: 64 t x 16 k, transposed to k-major
        {
            float4 v = *(const float4*)(tbase + (size_t)trow * DIM + kc + tq * 4);
            sT[tq * 4 + 0][trow] = v.x;
            sT[tq * 4 + 1][trow] = v.y;
            sT[tq * 4 + 2][trow] = v.z;
            sT[tq * 4 + 3][trow] = v.w;
        }
        // Load image chunk: 196 i x 16 k, transposed to k-major
        for (int idx = tid; idx < ITOK * 4; idx += 256) {
            int i = idx >> 2;
            int q = idx & 3;
            float4 v = *(const float4*)(ibase + (size_t)i * DIM + kc + q * 4);
            sI[q * 4 + 0][i] = v.x;
            sI[q * 4 + 1][i] = v.y;
            sI[q * 4 + 2][i] = v.z;
            sI[q * 4 + 3][i] = v.w;
        }
        __syncthreads();

#pragma unroll
        for (int k = 0; k < 16; ++k) {
            float4 a = *(const float4*)&sT[k][ty * 4];
            float bv[13];
#pragma unroll
            for (int c = 0; c < 13; ++c) bv[c] = sI[k][tx + 16 * c];
#pragma unroll
            for (int c = 0; c < 13; ++c) {
                acc[0][c] = fmaf(a.x, bv[c], acc[0][c]);
                acc[1][c] = fmaf(a.y, bv[c], acc[1][c]);
                acc[2][c] = fmaf(a.z, bv[c], acc[2][c]);
                acc[3][c] = fmaf(a.w, bv[c], acc[3][c]);
            }
        }
    }

    // Max over this thread's i-columns (valid: i = tx + 16c < 196)
    float m[4];
#pragma unroll
    for (int r = 0; r < 4; ++r) {
        float v = acc[r][0];
#pragma unroll
        for (int c = 1; c < 12; ++c) v = fmaxf(v, acc[r][c]);
        if (tx < 4) v = fmaxf(v, acc[r][12]);   // c=12 -> i = 192+tx, valid iff tx<4
        // Max across the 16 tx lanes (bits 0..3 of lane id)
#pragma unroll
        for (int off = 1; off <= 8; off <<= 1)
            v = fmaxf(v, __shfl_xor_sync(0xffffffffu, v, off));
        m[r] = v;
    }
    if (tx == 0) {
#pragma unroll
        for (int r = 0; r < 4; ++r) tmax[ty * 4 + r] = m[r];
    }
    __syncthreads();
    if (tid == 0) {
        float s = 0.0f;
        for (int t = 0; t < TTOK; ++t) s += tmax[t];
        g_S[b1 * BATCH + b2] = s * (1.0f / TTOK);
    }
}

// Symmetric InfoNCE over the 128x128 logit matrix. One block, 128 threads.
__global__ void loss_kernel(float* __restrict__ out) {
    __shared__ float red[BATCH];
    const int b = threadIdx.x;
    const float invT = 1.0f / TEMP;

    float rmax = -INFINITY, cmax = -INFINITY;
    for (int j = 0; j < BATCH; ++j) {
        rmax = fmaxf(rmax, g_S[b * BATCH + j]);
        cmax = fmaxf(cmax, g_S[j * BATCH + b]);
    }
    float rs = 0.0f, cs = 0.0f;
    for (int j = 0; j < BATCH; ++j) {
        rs += expf((g_S[b * BATCH + j] - rmax) * invT);
        cs += expf((g_S[j * BATCH + b] - cmax) * invT);
    }
    float diag = g_S[b * BATCH + b] * invT;
    float rlse = rmax * invT + logf(rs);
    float clse = cmax * invT + logf(cs);
    red[b] = 0.5f * ((rlse - diag) + (clse - diag));
    __syncthreads();

    // Tree-reduce 128 values
    for (int s = 64; s > 0; s >>= 1) {
        if (b < s) red[b] += red[b + s];
        __syncthreads();
    }
    if (b == 0) out[0] = red[0] * (1.0f / BATCH);
}

extern "C" void kernel_launch(void* const* d_in, const int* in_sizes, int n_in,
                              void* d_out, int out_size) {
    const float* image = (const float*)d_in[0];   // [128, 196, 512] f32
    const float* text  = (const float*)d_in[1];   // [128,  64, 512] f32

    maxsim_kernel<<<dim3(BATCH, BATCH), 256>>>(image, text);
    loss_kernel<<<1, BATCH>>>((float*)d_out);
}

// round 3
// speedup vs baseline: 3.2897x; 3.2897x over previous
#include <cuda_runtime.h>
#include <cuda_fp16.h>
#include <cstdint>
#include <math.h>

#define BATCH 128
#define TTOK  64
#define ITOK  196
#define DIM   512
#define TEMP  0.07f

#define MROWS 128
#define KC    64
#define NCHUNK (DIM / KC)   // 8
#define NTHREADS 512

// per-stage smem layout (bytes); rows are 128B (64 halves), SW128-swizzled
#define AHI 0
#define ALO 16384
#define BHI 32768
#define BLO 58368            // BHI + 200 rows * 128
#define STAGE 83968
#define SMEM_BYTES (2 * STAGE)   // 167936

__device__ __align__(16) __half g_text_hi[BATCH * TTOK * DIM];
__device__ __align__(16) __half g_text_lo[BATCH * TTOK * DIM];
__device__ __align__(16) __half g_img_hi[BATCH * ITOK * DIM];
__device__ __align__(16) __half g_img_lo[BATCH * ITOK * DIM];
__device__ float g_S[BATCH * BATCH];

// ---------------- helpers ----------------
__device__ __forceinline__ uint32_t smem_u32(const void* p) {
    uint32_t a;
    asm("{ .reg .u64 t; cvta.to.shared.u64 t, %1; cvt.u32.u64 %0, t; }" : "=r"(a) : "l"(p));
    return a;
}
__device__ __forceinline__ uint32_t sw_off(int row, int koff) {
    // row*128 byte rows, SW128: swizzle 16B chunk index by (row&7)
    return (uint32_t)(row * 128 + (koff ^ ((row & 7) << 4)));
}
__device__ __forceinline__ void cp16(uint32_t dst, const void* src) {
    asm volatile("cp.async.cg.shared.global [%0], [%1], 16;" :: "r"(dst), "l"(src) : "memory");
}
#define CP_COMMIT() asm volatile("cp.async.commit_group;" ::: "memory")
#define CP_WAIT1()  asm volatile("cp.async.wait_group 1;" ::: "memory")
#define CP_WAIT0()  asm volatile("cp.async.wait_group 0;" ::: "memory")

__device__ __forceinline__ void ldsm_x4(uint32_t (&r)[4], uint32_t addr) {
    asm volatile("ldmatrix.sync.aligned.m8n8.x4.shared.b16 {%0,%1,%2,%3}, [%4];"
                 : "=r"(r[0]), "=r"(r[1]), "=r"(r[2]), "=r"(r[3]) : "r"(addr));
}
__device__ __forceinline__ void ldsm_x2(uint32_t (&r)[2], uint32_t addr) {
    asm volatile("ldmatrix.sync.aligned.m8n8.x2.shared.b16 {%0,%1}, [%2];"
                 : "=r"(r[0]), "=r"(r[1]) : "r"(addr));
}
__device__ __forceinline__ void mma16816(float (&d)[4], const uint32_t (&a)[4],
                                         const uint32_t* b) {
    asm volatile(
        "mma.sync.aligned.m16n8k16.row.col.f32.f16.f16.f32 "
        "{%0,%1,%2,%3}, {%4,%5,%6,%7}, {%8,%9}, {%0,%1,%2,%3};"
        : "+f"(d[0]), "+f"(d[1]), "+f"(d[2]), "+f"(d[3])
        : "r"(a[0]), "r"(a[1]), "r"(a[2]), "r"(a[3]), "r"(b[0]), "r"(b[1]));
}

// ---------------- f32 -> (hi, lo) fp16 split ----------------
__global__ void convert_kernel(const float* __restrict__ src,
                               __half* __restrict__ hi,
                               __half* __restrict__ lo, int n4) {
    int i = blockIdx.x * blockDim.x + threadIdx.x;
    if (i >= n4) return;
    float4 v = ((const float4*)src)[i];
    float x[4] = {v.x, v.y, v.z, v.w};
    unsigned short hs[4], ls[4];
#pragma unroll
    for (int j = 0; j < 4; ++j) {
        __half hb = __float2half_rn(x[j]);
        float r = x[j] - __half2float(hb);
        __half lb = __float2half_rn(r);
        hs[j] = __half_as_ushort(hb);
        ls[j] = __half_as_ushort(lb);
    }
    ushort4 h = {hs[0], hs[1], hs[2], hs[3]};
    ushort4 l2 = {ls[0], ls[1], ls[2], ls[3]};
    ((ushort4*)hi)[i] = h;
    ((ushort4*)lo)[i] = l2;
}

// ---------------- chunk loader (cp.async) ----------------
__device__ __forceinline__ void load_chunk(uint32_t su_s, int ch, int tid,
                                           int trow0, int irow0) {
    const uint4* thi = (const uint4*)g_text_hi;
    const uint4* tlo = (const uint4*)g_text_lo;
    const uint4* ihi = (const uint4*)g_img_hi;
    const uint4* ilo = (const uint4*)g_img_lo;
    // A: 128 rows x 8 16B-chunks, hi + lo
#pragma unroll
    for (int idx = tid; idx < 1024; idx += NTHREADS) {
        int r = idx >> 3, kq = idx & 7;
        uint32_t d = sw_off(r, kq * 16);
        size_t g = (size_t)(trow0 + r) * 64 + ch * 8 + kq;
        cp16(su_s + AHI + d, thi + g);
        cp16(su_s + ALO + d, tlo + g);
    }
    // B: 196 rows x 8 chunks, hi + lo
#pragma unroll
    for (int idx = tid; idx < 1568; idx += NTHREADS) {
        int r = idx >> 3, kq = idx & 7;
        uint32_t d = sw_off(r, kq * 16);
        size_t g = (size_t)(irow0 + r) * 64 + ch * 8 + kq;
        cp16(su_s + BHI + d, ihi + g);
        cp16(su_s + BLO + d, ilo + g);
    }
}

// ---------------- per-chunk compute, NT n8-tiles active ----------------
template <int NT>
__device__ __forceinline__ void compute_chunk(
    uint32_t sa_hi, uint32_t sa_lo, uint32_t sb_hi, uint32_t sb_lo,
    int a_row, int a_kl, int b_prow, int b_kl, int b_lrow,
    float (&acc)[2][7][4]) {
#pragma unroll
    for (int ks = 0; ks < 4; ++ks) {
        const int koff = ks * 32;
        uint32_t aH[2][4], aL[2][4];
#pragma unroll
        for (int mt = 0; mt < 2; ++mt) {
            uint32_t off = sw_off(a_row + mt * 16, koff + a_kl);
            ldsm_x4(aH[mt], sa_hi + off);
            ldsm_x4(aL[mt], sa_lo + off);
        }
        uint32_t bH[7][2], bL[7][2];
#pragma unroll
        for (int p = 0; p * 2 + 1 < NT; ++p) {
            uint32_t off = sw_off(b_prow + p * 16, koff + b_kl);
            uint32_t r4[4];
            ldsm_x4(r4, sb_hi + off);
            bH[p * 2][0] = r4[0]; bH[p * 2][1] = r4[1];
            bH[p * 2 + 1][0] = r4[2]; bH[p * 2 + 1][1] = r4[3];
            ldsm_x4(r4, sb_lo + off);
            bL[p * 2][0] = r4[0]; bL[p * 2][1] = r4[1];
            bL[p * 2 + 1][0] = r4[2]; bL[p * 2 + 1][1] = r4[3];
        }
        if (NT & 1) {
            uint32_t off = sw_off(b_lrow, koff + b_kl);
            uint32_t r2[2];
            ldsm_x2(r2, sb_hi + off);
            bH[NT - 1][0] = r2[0]; bH[NT - 1][1] = r2[1];
            ldsm_x2(r2, sb_lo + off);
            bL[NT - 1][0] = r2[0]; bL[NT - 1][1] = r2[1];
        }
#pragma unroll
        for (int mt = 0; mt < 2; ++mt)
#pragma unroll
            for (int nt = 0; nt < NT; ++nt) {
                mma16816(acc[mt][nt], aH[mt], bH[nt]);
                mma16816(acc[mt][nt], aH[mt], bL[nt]);
                mma16816(acc[mt][nt], aL[mt], bH[nt]);
            }
    }
}

// ---------------- maxsim GEMM kernel ----------------
// grid (b2=128, mtile=64); 512 threads = 16 warps = 4 m-groups x 4 n-groups.
__global__ __launch_bounds__(NTHREADS, 1)
void maxsim_mma_kernel() {
    extern __shared__ __align__(1024) char smem[];
    const int tid = threadIdx.x;
    const int b2 = blockIdx.x, mtile = blockIdx.y;
    const int trow0 = mtile * MROWS, irow0 = b2 * ITOK;
    const uint32_t su = smem_u32(smem);
    const int w = tid >> 5, l = tid & 31;
    const int w_m = w >> 2, w_n = w & 3;

    // lane geometry for ldmatrix
    const int a_row  = w_m * 32 + (l & 15);
    const int a_kl   = (l >> 4) * 16;
    const int b_prow = w_n * 56 + ((l >> 4) << 3) + (l & 7);
    const int b_kl   = ((l >> 3) & 1) * 16;
    const int b_lrow = w_n * 56 + 48 + (l & 7);

    float acc[2][7][4];
#pragma unroll
    for (int a = 0; a < 2; ++a)
#pragma unroll
        for (int b = 0; b < 7; ++b)
#pragma unroll
            for (int c = 0; c < 4; ++c) acc[a][b][c] = 0.0f;

    load_chunk(su, 0, tid, trow0, irow0);
    CP_COMMIT();

    for (int ch = 0; ch < NCHUNK; ++ch) {
        if (ch + 1 < NCHUNK) {
            load_chunk(su + ((ch + 1) & 1) * STAGE, ch + 1, tid, trow0, irow0);
            CP_COMMIT();
            CP_WAIT1();
        } else {
            CP_WAIT0();
        }
        __syncthreads();
        const uint32_t sb = su + (ch & 1) * STAGE;
        if (w_n == 3)
            compute_chunk<4>(sb + AHI, sb + ALO, sb + BHI, sb + BLO,
                             a_row, a_kl, b_prow, b_kl, b_lrow, acc);
        else
            compute_chunk<7>(sb + AHI, sb + ALO, sb + BHI, sb + BLO,
                             a_row, a_kl, b_prow, b_kl, b_lrow, acc);
        __syncthreads();
    }

    // ---- epilogue: max over image cols (masked >=196), then mean over text rows
    __shared__ float s_nmax[4][128];
    __shared__ float s_red[4];
    const int NTa = (w_n == 3) ? 4 : 7;

    float rm[2][2];
    rm[0][0] = rm[0][1] = rm[1][0] = rm[1][1] = -INFINITY;
#pragma unroll
    for (int mt = 0; mt < 2; ++mt)
        for (int nt = 0; nt < 7; ++nt) {
            if (nt >= NTa) break;
#pragma unroll
            for (int h = 0; h < 2; ++h)
#pragma unroll
                for (int j = 0; j < 2; ++j) {
                    int col = w_n * 56 + nt * 8 + (l & 3) * 2 + j;
                    if (col < ITOK)
                        rm[mt][h] = fmaxf(rm[mt][h], acc[mt][nt][h * 2 + j]);
                }
        }
    // reduce across the 4 lanes sharing a row (same l>>2)
#pragma unroll
    for (int off = 1; off <= 2; off <<= 1)
#pragma unroll
        for (int mt = 0; mt < 2; ++mt)
#pragma unroll
            for (int h = 0; h < 2; ++h)
                rm[mt][h] = fmaxf(rm[mt][h], __shfl_xor_sync(0xffffffffu, rm[mt][h], off));
    if ((l & 3) == 0) {
#pragma unroll
        for (int mt = 0; mt < 2; ++mt)
#pragma unroll
            for (int h = 0; h < 2; ++h)
                s_nmax[w_n][w_m * 32 + mt * 16 + (l >> 2) + h * 8] = rm[mt][h];
    }
    __syncthreads();

    if (tid < 128) {
        float m = fmaxf(fmaxf(s_nmax[0][tid], s_nmax[1][tid]),
                        fmaxf(s_nmax[2][tid], s_nmax[3][tid]));
#pragma unroll
        for (int off = 16; off > 0; off >>= 1)
            m += __shfl_xor_sync(0xffffffffu, m, off);
        if ((tid & 31) == 0) s_red[tid >> 5] = m;
    }
    __syncthreads();
    if (tid == 0) {
        g_S[(mtile * 2 + 0) * BATCH + b2] = (s_red[0] + s_red[1]) * (1.0f / TTOK);
        g_S[(mtile * 2 + 1) * BATCH + b2] = (s_red[2] + s_red[3]) * (1.0f / TTOK);
    }
}

// ---------------- symmetric InfoNCE ----------------
__global__ void loss_kernel(float* __restrict__ out) {
    __shared__ float red[BATCH];
    const int b = threadIdx.x;
    const float invT = 1.0f / TEMP;

    float rmax = -INFINITY, cmax = -INFINITY;
    for (int j = 0; j < BATCH; ++j) {
        rmax = fmaxf(rmax, g_S[b * BATCH + j]);
        cmax = fmaxf(cmax, g_S[j * BATCH + b]);
    }
    float rs = 0.0f, cs = 0.0f;
    for (int j = 0; j < BATCH; ++j) {
        rs += expf((g_S[b * BATCH + j] - rmax) * invT);
        cs += expf((g_S[j * BATCH + b] - cmax) * invT);
    }
    float diag = g_S[b * BATCH + b] * invT;
    float rlse = rmax * invT + logf(rs);
    float clse = cmax * invT + logf(cs);
    red[b] = 0.5f * ((rlse - diag) + (clse - diag));
    __syncthreads();
    for (int s = 64; s > 0; s >>= 1) {
        if (b < s) red[b] += red[b + s];
        __syncthreads();
    }
    if (b == 0) out[0] = red[0] * (1.0f / BATCH);
}

extern "C" void kernel_launch(void* const* d_in, const int* in_sizes, int n_in,
                              void* d_out, int out_size) {
    const float* image = (const float*)d_in[0];   // [128, 196, 512]
    const float* text  = (const float*)d_in[1];   // [128,  64, 512]

    __half *thi, *tlo, *ihi, *ilo;
    cudaGetSymbolAddress((void**)&thi, g_text_hi);
    cudaGetSymbolAddress((void**)&tlo, g_text_lo);
    cudaGetSymbolAddress((void**)&ihi, g_img_hi);
    cudaGetSymbolAddress((void**)&ilo, g_img_lo);

    const int nt4 = BATCH * TTOK * DIM / 4;
    const int ni4 = BATCH * ITOK * DIM / 4;
    convert_kernel<<<(nt4 + 255) / 256, 256>>>(text, thi, tlo, nt4);
    convert_kernel<<<(ni4 + 255) / 256, 256>>>(image, ihi, ilo, ni4);

    cudaFuncSetAttribute(maxsim_mma_kernel,
                         cudaFuncAttributeMaxDynamicSharedMemorySize, SMEM_BYTES);
    maxsim_mma_kernel<<<dim3(BATCH, BATCH * TTOK / MROWS), NTHREADS, SMEM_BYTES>>>();

    loss_kernel<<<1, BATCH>>>((float*)d_out);
}

// round 4
// speedup vs baseline: 3.4833x; 1.0589x over previous
#include <cuda_runtime.h>
#include <cuda_fp16.h>
#include <cstdint>
#include <math.h>

#define BATCH 128
#define TTOK  64
#define ITOK  196
#define DIM   512
#define TEMP  0.07f

#define MROWS 128
#define KC    64
#define NCHUNK (DIM / KC)   // 8
#define NTHREADS 512

// per-stage smem layout (bytes); rows are 128B (64 halves), SW128-swizzled
#define AHI 0
#define ALO 16384
#define BHI 32768
#define BLO 58368            // BHI + 200 rows * 128
#define STAGE 83968
#define SMEM_BYTES (2 * STAGE)   // 167936

__device__ __align__(16) __half g_text_hi[BATCH * TTOK * DIM];
__device__ __align__(16) __half g_text_lo[BATCH * TTOK * DIM];
__device__ __align__(16) __half g_img_hi[BATCH * ITOK * DIM];
__device__ __align__(16) __half g_img_lo[BATCH * ITOK * DIM];
__device__ float g_S[BATCH * BATCH];

// ---------------- helpers ----------------
__device__ __forceinline__ uint32_t smem_u32(const void* p) {
    uint32_t a;
    asm("{ .reg .u64 t; cvta.to.shared.u64 t, %1; cvt.u32.u64 %0, t; }" : "=r"(a) : "l"(p));
    return a;
}
__device__ __forceinline__ uint32_t sw_off(int row, int koff) {
    return (uint32_t)(row * 128 + (koff ^ ((row & 7) << 4)));
}
__device__ __forceinline__ void cp16(uint32_t dst, const void* src) {
    asm volatile("cp.async.cg.shared.global [%0], [%1], 16;" :: "r"(dst), "l"(src) : "memory");
}
#define CP_COMMIT() asm volatile("cp.async.commit_group;" ::: "memory")
#define CP_WAIT1()  asm volatile("cp.async.wait_group 1;" ::: "memory")
#define CP_WAIT0()  asm volatile("cp.async.wait_group 0;" ::: "memory")

__device__ __forceinline__ void ldsm_x4(uint32_t (&r)[4], uint32_t addr) {
    asm volatile("ldmatrix.sync.aligned.m8n8.x4.shared.b16 {%0,%1,%2,%3}, [%4];"
                 : "=r"(r[0]), "=r"(r[1]), "=r"(r[2]), "=r"(r[3]) : "r"(addr));
}
__device__ __forceinline__ void ldsm_x2(uint32_t (&r)[2], uint32_t addr) {
    asm volatile("ldmatrix.sync.aligned.m8n8.x2.shared.b16 {%0,%1}, [%2];"
                 : "=r"(r[0]), "=r"(r[1]) : "r"(addr));
}
__device__ __forceinline__ void mma16816(float (&d)[4], const uint32_t (&a)[4],
                                         const uint32_t* b) {
    asm volatile(
        "mma.sync.aligned.m16n8k16.row.col.f32.f16.f16.f32 "
        "{%0,%1,%2,%3}, {%4,%5,%6,%7}, {%8,%9}, {%0,%1,%2,%3};"
        : "+f"(d[0]), "+f"(d[1]), "+f"(d[2]), "+f"(d[3])
        : "r"(a[0]), "r"(a[1]), "r"(a[2]), "r"(a[3]), "r"(b[0]), "r"(b[1]));
}

// ---------------- f32 -> (hi, lo) fp16 split ----------------
__global__ void convert_kernel(const float* __restrict__ src,
                               __half* __restrict__ hi,
                               __half* __restrict__ lo, int n4) {
    int i = blockIdx.x * blockDim.x + threadIdx.x;
    if (i >= n4) return;
    float4 v = ((const float4*)src)[i];
    float x[4] = {v.x, v.y, v.z, v.w};
    unsigned short hs[4], ls[4];
#pragma unroll
    for (int j = 0; j < 4; ++j) {
        __half hb = __float2half_rn(x[j]);
        float r = x[j] - __half2float(hb);
        __half lb = __float2half_rn(r);
        hs[j] = __half_as_ushort(hb);
        ls[j] = __half_as_ushort(lb);
    }
    ushort4 h = {hs[0], hs[1], hs[2], hs[3]};
    ushort4 l2 = {ls[0], ls[1], ls[2], ls[3]};
    ((ushort4*)hi)[i] = h;
    ((ushort4*)lo)[i] = l2;
}

// ---------------- chunk loader (cp.async) ----------------
__device__ __forceinline__ void load_chunk(uint32_t su_s, int ch, int tid,
                                           int trow0, int irow0) {
    const uint4* thi = (const uint4*)g_text_hi;
    const uint4* tlo = (const uint4*)g_text_lo;
    const uint4* ihi = (const uint4*)g_img_hi;
    const uint4* ilo = (const uint4*)g_img_lo;
#pragma unroll
    for (int idx = tid; idx < 1024; idx += NTHREADS) {
        int r = idx >> 3, kq = idx & 7;
        uint32_t d = sw_off(r, kq * 16);
        size_t g = (size_t)(trow0 + r) * 64 + ch * 8 + kq;
        cp16(su_s + AHI + d, thi + g);
        cp16(su_s + ALO + d, tlo + g);
    }
#pragma unroll
    for (int idx = tid; idx < 1568; idx += NTHREADS) {
        int r = idx >> 3, kq = idx & 7;
        uint32_t d = sw_off(r, kq * 16);
        size_t g = (size_t)(irow0 + r) * 64 + ch * 8 + kq;
        cp16(su_s + BHI + d, ihi + g);
        cp16(su_s + BLO + d, ilo + g);
    }
}

// ---------------- per-chunk compute; B tiles streamed in pairs ----------------
template <int NT>
__device__ __forceinline__ void compute_chunk(
    uint32_t sa_hi, uint32_t sa_lo, uint32_t sb_hi, uint32_t sb_lo,
    int a_row, int a_kl, int b_prow, int b_kl, int b_lrow,
    float (&acc)[2][7][4]) {
#pragma unroll
    for (int ks = 0; ks < 4; ++ks) {
        const int koff = ks * 32;
        uint32_t aH[2][4], aL[2][4];
#pragma unroll
        for (int mt = 0; mt < 2; ++mt) {
            uint32_t off = sw_off(a_row + mt * 16, koff + a_kl);
            ldsm_x4(aH[mt], sa_hi + off);
            ldsm_x4(aL[mt], sa_lo + off);
        }
#pragma unroll
        for (int p = 0; p < NT / 2; ++p) {
            uint32_t off = sw_off(b_prow + p * 16, koff + b_kl);
            uint32_t bh[4], bl[4];
            ldsm_x4(bh, sb_hi + off);
            ldsm_x4(bl, sb_lo + off);
#pragma unroll
            for (int mt = 0; mt < 2; ++mt) {
                mma16816(acc[mt][2 * p],     aH[mt], bh + 0);
                mma16816(acc[mt][2 * p + 1], aH[mt], bh + 2);
                mma16816(acc[mt][2 * p],     aH[mt], bl + 0);
                mma16816(acc[mt][2 * p + 1], aH[mt], bl + 2);
                mma16816(acc[mt][2 * p],     aL[mt], bh + 0);
                mma16816(acc[mt][2 * p + 1], aL[mt], bh + 2);
            }
        }
        if (NT & 1) {
            uint32_t off = sw_off(b_lrow, koff + b_kl);
            uint32_t bh[2], bl[2];
            ldsm_x2(bh, sb_hi + off);
            ldsm_x2(bl, sb_lo + off);
#pragma unroll
            for (int mt = 0; mt < 2; ++mt) {
                mma16816(acc[mt][NT - 1], aH[mt], bh);
                mma16816(acc[mt][NT - 1], aH[mt], bl);
                mma16816(acc[mt][NT - 1], aL[mt], bh);
            }
        }
    }
}

// ---------------- maxsim GEMM kernel ----------------
// grid (mtile=64, b2=128): image batch is SLOW index -> per-wave image footprint
// ~2 batches, text stays L2-resident across all waves.
__global__ __launch_bounds__(NTHREADS, 1)
void maxsim_mma_kernel() {
    extern __shared__ __align__(1024) char smem[];
    const int tid = threadIdx.x;
    const int mtile = blockIdx.x, b2 = blockIdx.y;
    const int trow0 = mtile * MROWS, irow0 = b2 * ITOK;
    const uint32_t su = smem_u32(smem);
    const int w = tid >> 5, l = tid & 31;
    const int w_m = w >> 2, w_n = w & 3;

    const int a_row  = w_m * 32 + (l & 15);
    const int a_kl   = (l >> 4) * 16;
    const int b_prow = w_n * 56 + ((l >> 4) << 3) + (l & 7);
    const int b_kl   = ((l >> 3) & 1) * 16;
    const int b_lrow = w_n * 56 + 48 + (l & 7);

    float acc[2][7][4];
#pragma unroll
    for (int a = 0; a < 2; ++a)
#pragma unroll
        for (int b = 0; b < 7; ++b)
#pragma unroll
            for (int c = 0; c < 4; ++c) acc[a][b][c] = 0.0f;

    load_chunk(su, 0, tid, trow0, irow0);
    CP_COMMIT();

    for (int ch = 0; ch < NCHUNK; ++ch) {
        if (ch + 1 < NCHUNK) {
            load_chunk(su + ((ch + 1) & 1) * STAGE, ch + 1, tid, trow0, irow0);
            CP_COMMIT();
            CP_WAIT1();
        } else {
            CP_WAIT0();
        }
        __syncthreads();
        const uint32_t sb = su + (ch & 1) * STAGE;
        if (w_n == 3)
            compute_chunk<4>(sb + AHI, sb + ALO, sb + BHI, sb + BLO,
                             a_row, a_kl, b_prow, b_kl, b_lrow, acc);
        else
            compute_chunk<7>(sb + AHI, sb + ALO, sb + BHI, sb + BLO,
                             a_row, a_kl, b_prow, b_kl, b_lrow, acc);
        __syncthreads();
    }

    // ---- epilogue: masked max over image cols, then mean over text rows
    __shared__ float s_nmax[4][128];
    __shared__ float s_red[4];
    const int NTa = (w_n == 3) ? 4 : 7;

    float rm[2][2];
    rm[0][0] = rm[0][1] = rm[1][0] = rm[1][1] = -INFINITY;
#pragma unroll
    for (int mt = 0; mt < 2; ++mt)
        for (int nt = 0; nt < 7; ++nt) {
            if (nt >= NTa) break;
#pragma unroll
            for (int h = 0; h < 2; ++h)
#pragma unroll
                for (int j = 0; j < 2; ++j) {
                    int col = w_n * 56 + nt * 8 + (l & 3) * 2 + j;
                    if (col < ITOK)
                        rm[mt][h] = fmaxf(rm[mt][h], acc[mt][nt][h * 2 + j]);
                }
        }
#pragma unroll
    for (int off = 1; off <= 2; off <<= 1)
#pragma unroll
        for (int mt = 0; mt < 2; ++mt)
#pragma unroll
            for (int h = 0; h < 2; ++h)
                rm[mt][h] = fmaxf(rm[mt][h], __shfl_xor_sync(0xffffffffu, rm[mt][h], off));
    if ((l & 3) == 0) {
#pragma unroll
        for (int mt = 0; mt < 2; ++mt)
#pragma unroll
            for (int h = 0; h < 2; ++h)
                s_nmax[w_n][w_m * 32 + mt * 16 + (l >> 2) + h * 8] = rm[mt][h];
    }
    __syncthreads();

    if (tid < 128) {
        float m = fmaxf(fmaxf(s_nmax[0][tid], s_nmax[1][tid]),
                        fmaxf(s_nmax[2][tid], s_nmax[3][tid]));
#pragma unroll
        for (int off = 16; off > 0; off >>= 1)
            m += __shfl_xor_sync(0xffffffffu, m, off);
        if ((tid & 31) == 0) s_red[tid >> 5] = m;
    }
    __syncthreads();
    if (tid == 0) {
        g_S[(mtile * 2 + 0) * BATCH + b2] = (s_red[0] + s_red[1]) * (1.0f / TTOK);
        g_S[(mtile * 2 + 1) * BATCH + b2] = (s_red[2] + s_red[3]) * (1.0f / TTOK);
    }
}

// ---------------- symmetric InfoNCE (1024 threads, 8 lanes per row) ------------
__global__ void loss_kernel(float* __restrict__ out) {
    __shared__ float s_red[BATCH];
    __shared__ float s_fin[4];
    const int tid = threadIdx.x;
    const int b = tid >> 3, s = tid & 7;
    const float invT = 1.0f / TEMP;

    float rv[16], cv[16];
#pragma unroll
    for (int j = 0; j < 16; ++j) {
        int jj = s * 16 + j;
        rv[j] = g_S[b * BATCH + jj];
        cv[j] = g_S[jj * BATCH + b];
    }
    float rmax = -INFINITY, cmax = -INFINITY;
#pragma unroll
    for (int j = 0; j < 16; ++j) {
        rmax = fmaxf(rmax, rv[j]);
        cmax = fmaxf(cmax, cv[j]);
    }
#pragma unroll
    for (int off = 1; off <= 4; off <<= 1) {
        rmax = fmaxf(rmax, __shfl_xor_sync(0xffffffffu, rmax, off));
        cmax = fmaxf(cmax, __shfl_xor_sync(0xffffffffu, cmax, off));
    }
    float rs = 0.0f, cs = 0.0f;
#pragma unroll
    for (int j = 0; j < 16; ++j) {
        rs += expf((rv[j] - rmax) * invT);
        cs += expf((cv[j] - cmax) * invT);
    }
#pragma unroll
    for (int off = 1; off <= 4; off <<= 1) {
        rs += __shfl_xor_sync(0xffffffffu, rs, off);
        cs += __shfl_xor_sync(0xffffffffu, cs, off);
    }
    if (s == 0) {
        float diag = g_S[b * BATCH + b] * invT;
        float rlse = rmax * invT + logf(rs);
        float clse = cmax * invT + logf(cs);
        s_red[b] = 0.5f * ((rlse - diag) + (clse - diag));
    }
    __syncthreads();
    if (tid < 128) {
        float v = s_red[tid];
#pragma unroll
        for (int off = 16; off > 0; off >>= 1)
            v += __shfl_xor_sync(0xffffffffu, v, off);
        if ((tid & 31) == 0) s_fin[tid >> 5] = v;
    }
    __syncthreads();
    if (tid == 0)
        out[0] = (s_fin[0] + s_fin[1] + s_fin[2] + s_fin[3]) * (1.0f / BATCH);
}

extern "C" void kernel_launch(void* const* d_in, const int* in_sizes, int n_in,
                              void* d_out, int out_size) {
    const float* image = (const float*)d_in[0];   // [128, 196, 512]
    const float* text  = (const float*)d_in[1];   // [128,  64, 512]

    __half *thi, *tlo, *ihi, *ilo;
    cudaGetSymbolAddress((void**)&thi, g_text_hi);
    cudaGetSymbolAddress((void**)&tlo, g_text_lo);
    cudaGetSymbolAddress((void**)&ihi, g_img_hi);
    cudaGetSymbolAddress((void**)&ilo, g_img_lo);

    const int nt4 = BATCH * TTOK * DIM / 4;
    const int ni4 = BATCH * ITOK * DIM / 4;
    convert_kernel<<<(nt4 + 255) / 256, 256>>>(text, thi, tlo, nt4);
    convert_kernel<<<(ni4 + 255) / 256, 256>>>(image, ihi, ilo, ni4);

    cudaFuncSetAttribute(maxsim_mma_kernel,
                         cudaFuncAttributeMaxDynamicSharedMemorySize, SMEM_BYTES);
    maxsim_mma_kernel<<<dim3(BATCH * TTOK / MROWS, BATCH), NTHREADS, SMEM_BYTES>>>();

    loss_kernel<<<1, 1024>>>((float*)d_out);
}

// round 6
// speedup vs baseline: 3.5652x; 1.0235x over previous
#include <cuda_runtime.h>
#include <cuda_fp16.h>
#include <cstdint>
#include <math.h>

#define BATCH 128
#define TTOK  64
#define ITOK  196
#define DIM   512
#define TEMP  0.07f

#define MROWS 128
#define KC    64
#define NCHUNK (DIM / KC)   // 8
#define NTHREADS 256

// per-stage smem layout (bytes); rows are 128B (64 halves), SW128-swizzled
#define AHI 0
#define ALO 16384
#define BHI 32768
#define BLO 58368            // BHI + 200 rows * 128
#define STAGE 83968
#define SMEM_BYTES (2 * STAGE)   // 167936

__device__ __align__(16) __half g_text_hi[BATCH * TTOK * DIM];
__device__ __align__(16) __half g_text_lo[BATCH * TTOK * DIM];
__device__ __align__(16) __half g_img_hi[BATCH * ITOK * DIM];
__device__ __align__(16) __half g_img_lo[BATCH * ITOK * DIM];
__device__ float g_S[BATCH * BATCH];

// ---------------- helpers ----------------
__device__ __forceinline__ uint32_t smem_u32(const void* p) {
    uint32_t a;
    asm("{ .reg .u64 t; cvta.to.shared.u64 t, %1; cvt.u32.u64 %0, t; }" : "=r"(a) : "l"(p));
    return a;
}
__device__ __forceinline__ uint32_t sw_off(int row, int koff) {
    return (uint32_t)(row * 128 + (koff ^ ((row & 7) << 4)));
}
__device__ __forceinline__ void cp16(uint32_t dst, const void* src) {
    asm volatile("cp.async.cg.shared.global [%0], [%1], 16;" :: "r"(dst), "l"(src) : "memory");
}
#define CP_COMMIT() asm volatile("cp.async.commit_group;" ::: "memory")
#define CP_WAIT0()  asm volatile("cp.async.wait_group 0;" ::: "memory")

__device__ __forceinline__ void ldsm_x4(uint32_t (&r)[4], uint32_t addr) {
    asm volatile("ldmatrix.sync.aligned.m8n8.x4.shared.b16 {%0,%1,%2,%3}, [%4];"
                 : "=r"(r[0]), "=r"(r[1]), "=r"(r[2]), "=r"(r[3]) : "r"(addr));
}
__device__ __forceinline__ void ldsm_x2(uint32_t (&r)[2], uint32_t addr) {
    asm volatile("ldmatrix.sync.aligned.m8n8.x2.shared.b16 {%0,%1}, [%2];"
                 : "=r"(r[0]), "=r"(r[1]) : "r"(addr));
}
__device__ __forceinline__ void mma16816(float (&d)[4], const uint32_t (&a)[4],
                                         const uint32_t* b) {
    asm volatile(
        "mma.sync.aligned.m16n8k16.row.col.f32.f16.f16.f32 "
        "{%0,%1,%2,%3}, {%4,%5,%6,%7}, {%8,%9}, {%0,%1,%2,%3};"
        : "+f"(d[0]), "+f"(d[1]), "+f"(d[2]), "+f"(d[3])
        : "r"(a[0]), "r"(a[1]), "r"(a[2]), "r"(a[3]), "r"(b[0]), "r"(b[1]));
}

// ---------------- f32 -> (hi, lo) fp16 split ----------------
__global__ void convert_kernel(const float* __restrict__ src,
                               __half* __restrict__ hi,
                               __half* __restrict__ lo, int n4) {
    int i = blockIdx.x * blockDim.x + threadIdx.x;
    if (i >= n4) return;
    float4 v = ((const float4*)src)[i];
    float x[4] = {v.x, v.y, v.z, v.w};
    unsigned short hs[4], ls[4];
#pragma unroll
    for (int j = 0; j < 4; ++j) {
        __half hb = __float2half_rn(x[j]);
        float r = x[j] - __half2float(hb);
        __half lb = __float2half_rn(r);
        hs[j] = __half_as_ushort(hb);
        ls[j] = __half_as_ushort(lb);
    }
    ushort4 h = {hs[0], hs[1], hs[2], hs[3]};
    ushort4 l2 = {ls[0], ls[1], ls[2], ls[3]};
    ((ushort4*)hi)[i] = h;
    ((ushort4*)lo)[i] = l2;
}

// ---------------- chunk loader (cp.async) ----------------
__device__ __forceinline__ void load_chunk(uint32_t su_s, int ch, int tid,
                                           int trow0, int irow0) {
    const uint4* thi = (const uint4*)g_text_hi;
    const uint4* tlo = (const uint4*)g_text_lo;
    const uint4* ihi = (const uint4*)g_img_hi;
    const uint4* ilo = (const uint4*)g_img_lo;
#pragma unroll
    for (int idx = tid; idx < 1024; idx += NTHREADS) {
        int r = idx >> 3, kq = idx & 7;
        uint32_t d = sw_off(r, kq * 16);
        size_t g = (size_t)(trow0 + r) * 64 + ch * 8 + kq;
        cp16(su_s + AHI + d, thi + g);
        cp16(su_s + ALO + d, tlo + g);
    }
#pragma unroll
    for (int idx = tid; idx < 1568; idx += NTHREADS) {
        int r = idx >> 3, kq = idx & 7;
        uint32_t d = sw_off(r, kq * 16);
        size_t g = (size_t)(irow0 + r) * 64 + ch * 8 + kq;
        cp16(su_s + BHI + d, ihi + g);
        cp16(su_s + BLO + d, ilo + g);
    }
}

// ---------------- per-chunk compute; 4 m-tiles, B streamed in pairs ----------
template <int NT>
__device__ __forceinline__ void compute_chunk(
    uint32_t sa_hi, uint32_t sa_lo, uint32_t sb_hi, uint32_t sb_lo,
    int a_row, int a_kl, int b_prow, int b_kl, int b_lrow,
    float (&acc)[4][7][4]) {
#pragma unroll
    for (int ks = 0; ks < 4; ++ks) {
        const int koff = ks * 32;
        uint32_t aH[4][4], aL[4][4];
#pragma unroll
        for (int mt = 0; mt < 4; ++mt) {
            uint32_t off = sw_off(a_row + mt * 16, koff + a_kl);
            ldsm_x4(aH[mt], sa_hi + off);
            ldsm_x4(aL[mt], sa_lo + off);
        }
#pragma unroll
        for (int p = 0; p < NT / 2; ++p) {
            uint32_t off = sw_off(b_prow + p * 16, koff + b_kl);
            uint32_t bh[4], bl[4];
            ldsm_x4(bh, sb_hi + off);
            ldsm_x4(bl, sb_lo + off);
#pragma unroll
            for (int mt = 0; mt < 4; ++mt) {
                mma16816(acc[mt][2 * p],     aH[mt], bh + 0);
                mma16816(acc[mt][2 * p + 1], aH[mt], bh + 2);
                mma16816(acc[mt][2 * p],     aH[mt], bl + 0);
                mma16816(acc[mt][2 * p + 1], aH[mt], bl + 2);
                mma16816(acc[mt][2 * p],     aL[mt], bh + 0);
                mma16816(acc[mt][2 * p + 1], aL[mt], bh + 2);
            }
        }
        if (NT & 1) {
            uint32_t off = sw_off(b_lrow, koff + b_kl);
            uint32_t bh[2], bl[2];
            ldsm_x2(bh, sb_hi + off);
            ldsm_x2(bl, sb_lo + off);
#pragma unroll
            for (int mt = 0; mt < 4; ++mt) {
                mma16816(acc[mt][NT - 1], aH[mt], bh);
                mma16816(acc[mt][NT - 1], aH[mt], bl);
                mma16816(acc[mt][NT - 1], aL[mt], bh);
            }
        }
    }
}

// ---------------- maxsim GEMM kernel ----------------
// grid (mtile=64, b2=128); 256 threads = 8 warps = 2 m-groups x 4 n-groups.
// Warp tile: 64 rows x 56 cols.
__global__ __launch_bounds__(NTHREADS, 1)
void maxsim_mma_kernel() {
    extern __shared__ __align__(1024) char smem[];
    const int tid = threadIdx.x;
    const int mtile = blockIdx.x, b2 = blockIdx.y;
    const int trow0 = mtile * MROWS, irow0 = b2 * ITOK;
    const uint32_t su = smem_u32(smem);
    const int w = tid >> 5, l = tid & 31;
    const int w_m = w >> 2, w_n = w & 3;

    const int a_row  = w_m * 64 + (l & 15);
    const int a_kl   = (l >> 4) * 16;
    const int b_prow = w_n * 56 + ((l >> 4) << 3) + (l & 7);
    const int b_kl   = ((l >> 3) & 1) * 16;
    const int b_lrow = w_n * 56 + 48 + (l & 7);

    float acc[4][7][4];
#pragma unroll
    for (int a = 0; a < 4; ++a)
#pragma unroll
        for (int b = 0; b < 7; ++b)
#pragma unroll
            for (int c = 0; c < 4; ++c) acc[a][b][c] = 0.0f;

    load_chunk(su, 0, tid, trow0, irow0);
    CP_COMMIT();

    // Single sync per chunk. Wait must be wait_group 0: at this point the
    // only pending group is chunk ch (ch+1 not yet issued).
    for (int ch = 0; ch < NCHUNK; ++ch) {
        CP_WAIT0();          // chunk ch landed
        __syncthreads();     // all warps finished reading buffer (ch+1)&1 (= ch-1)
        if (ch + 1 < NCHUNK) {
            load_chunk(su + ((ch + 1) & 1) * STAGE, ch + 1, tid, trow0, irow0);
            CP_COMMIT();     // overlaps with compute below
        }
        const uint32_t sb = su + (ch & 1) * STAGE;
        if (w_n == 3)
            compute_chunk<4>(sb + AHI, sb + ALO, sb + BHI, sb + BLO,
                             a_row, a_kl, b_prow, b_kl, b_lrow, acc);
        else
            compute_chunk<7>(sb + AHI, sb + ALO, sb + BHI, sb + BLO,
                             a_row, a_kl, b_prow, b_kl, b_lrow, acc);
    }

    // ---- epilogue: masked max over image cols, then mean over text rows
    __shared__ float s_nmax[4][128];
    __shared__ float s_red[4];
    const int NTa = (w_n == 3) ? 4 : 7;

    float rm[4][2];
#pragma unroll
    for (int mt = 0; mt < 4; ++mt) { rm[mt][0] = -INFINITY; rm[mt][1] = -INFINITY; }
#pragma unroll
    for (int mt = 0; mt < 4; ++mt)
        for (int nt = 0; nt < 7; ++nt) {
            if (nt >= NTa) break;
#pragma unroll
            for (int h = 0; h < 2; ++h)
#pragma unroll
                for (int j = 0; j < 2; ++j) {
                    int col = w_n * 56 + nt * 8 + (l & 3) * 2 + j;
                    if (col < ITOK)
                        rm[mt][h] = fmaxf(rm[mt][h], acc[mt][nt][h * 2 + j]);
                }
        }
#pragma unroll
    for (int off = 1; off <= 2; off <<= 1)
#pragma unroll
        for (int mt = 0; mt < 4; ++mt)
#pragma unroll
            for (int h = 0; h < 2; ++h)
                rm[mt][h] = fmaxf(rm[mt][h], __shfl_xor_sync(0xffffffffu, rm[mt][h], off));
    if ((l & 3) == 0) {
#pragma unroll
        for (int mt = 0; mt < 4; ++mt)
#pragma unroll
            for (int h = 0; h < 2; ++h)
                s_nmax[w_n][w_m * 64 + mt * 16 + (l >> 2) + h * 8] = rm[mt][h];
    }
    __syncthreads();

    if (tid < 128) {
        float m = fmaxf(fmaxf(s_nmax[0][tid], s_nmax[1][tid]),
                        fmaxf(s_nmax[2][tid], s_nmax[3][tid]));
#pragma unroll
        for (int off = 16; off > 0; off >>= 1)
            m += __shfl_xor_sync(0xffffffffu, m, off);
        if ((tid & 31) == 0) s_red[tid >> 5] = m;
    }
    __syncthreads();
    if (tid == 0) {
        g_S[(mtile * 2 + 0) * BATCH + b2] = (s_red[0] + s_red[1]) * (1.0f / TTOK);
        g_S[(mtile * 2 + 1) * BATCH + b2] = (s_red[2] + s_red[3]) * (1.0f / TTOK);
    }
}

// ---------------- symmetric InfoNCE (1024 threads, 8 lanes per row) ------------
__global__ void loss_kernel(float* __restrict__ out) {
    __shared__ float s_red[BATCH];
    __shared__ float s_fin[4];
    const int tid = threadIdx.x;
    const int b = tid >> 3, s = tid & 7;
    const float invT = 1.0f / TEMP;

    float rv[16], cv[16];
#pragma unroll
    for (int j = 0; j < 16; ++j) {
        int jj = s * 16 + j;
        rv[j] = g_S[b * BATCH + jj];
        cv[j] = g_S[jj * BATCH + b];
    }
    float rmax = -INFINITY, cmax = -INFINITY;
#pragma unroll
    for (int j = 0; j < 16; ++j) {
        rmax = fmaxf(rmax, rv[j]);
        cmax = fmaxf(cmax, cv[j]);
    }
#pragma unroll
    for (int off = 1; off <= 4; off <<= 1) {
        rmax = fmaxf(rmax, __shfl_xor_sync(0xffffffffu, rmax, off));
        cmax = fmaxf(cmax, __shfl_xor_sync(0xffffffffu, cmax, off));
    }
    float rs = 0.0f, cs = 0.0f;
#pragma unroll
    for (int j = 0; j < 16; ++j) {
        rs += expf((rv[j] - rmax) * invT);
        cs += expf((cv[j] - cmax) * invT);
    }
#pragma unroll
    for (int off = 1; off <= 4; off <<= 1) {
        rs += __shfl_xor_sync(0xffffffffu, rs, off);
        cs += __shfl_xor_sync(0xffffffffu, cs, off);
    }
    if (s == 0) {
        float diag = g_S[b * BATCH + b] * invT;
        float rlse = rmax * invT + logf(rs);
        float clse = cmax * invT + logf(cs);
        s_red[b] = 0.5f * ((rlse - diag) + (clse - diag));
    }
    __syncthreads();
    if (tid < 128) {
        float v = s_red[tid];
#pragma unroll
        for (int off = 16; off > 0; off >>= 1)
            v += __shfl_xor_sync(0xffffffffu, v, off);
        if ((tid & 31) == 0) s_fin[tid >> 5] = v;
    }
    __syncthreads();
    if (tid == 0)
        out[0] = (s_fin[0] + s_fin[1] + s_fin[2] + s_fin[3]) * (1.0f / BATCH);
}

extern "C" void kernel_launch(void* const* d_in, const int* in_sizes, int n_in,
                              void* d_out, int out_size) {
    const float* image = (const float*)d_in[0];   // [128, 196, 512]
    const float* text  = (const float*)d_in[1];   // [128,  64, 512]

    __half *thi, *tlo, *ihi, *ilo;
    cudaGetSymbolAddress((void**)&thi, g_text_hi);
    cudaGetSymbolAddress((void**)&tlo, g_text_lo);
    cudaGetSymbolAddress((void**)&ihi, g_img_hi);
    cudaGetSymbolAddress((void**)&ilo, g_img_lo);

    const int nt4 = BATCH * TTOK * DIM / 4;
    const int ni4 = BATCH * ITOK * DIM / 4;
    convert_kernel<<<(nt4 + 255) / 256, 256>>>(text, thi, tlo, nt4);
    convert_kernel<<<(ni4 + 255) / 256, 256>>>(image, ihi, ilo, ni4);

    cudaFuncSetAttribute(maxsim_mma_kernel,
                         cudaFuncAttributeMaxDynamicSharedMemorySize, SMEM_BYTES);
    maxsim_mma_kernel<<<dim3(BATCH * TTOK / MROWS, BATCH), NTHREADS, SMEM_BYTES>>>();

    loss_kernel<<<1, 1024>>>((float*)d_out);
}